// round 4
// baseline (speedup 1.0000x reference)
#include <cuda_runtime.h>
#include <cuda_fp16.h>

#define NBLK 128
#define NTHR 256
#define T_STEPS 512
#define PLEN 64

#define BK 64                 // k-halves per stage
#define RING 8                // cp.async pipeline depth
#define LA 6                  // lookahead (stages in flight)
#define SA 72                 // smem row stride (halves)
#define ASTAGE (64 * SA)
#define BSTAGE (32 * SA)
#define GATES_OFF (RING * (ASTAGE + BSTAGE))                 // in halves
#define WFC_OFF   (GATES_OFF + 64 * 33 * 2)                  // gates = 64*33 floats
#define SMEM_BYTES ((WFC_OFF + 8 * 1024) * 2)

// ---------------- device state ----------------
__device__ __half g_Wp0[128 * 18 * 2048];   // layer0 packed (K: 16 H-stages + 2 X-stages)
__device__ __half g_Wp1[128 * 32 * 2048];   // layer1 packed (16 H + 16 X)
__device__ __half g_Wp2[128 * 32 * 2048];
__device__ __half g_Wfch[128 * 1024];
__device__ float  g_bsum[3 * 4096];
__device__ __half g_In0[64 * 128];
__device__ __half g_X1[64 * 1024];
__device__ __half g_X2[64 * 1024];
__device__ __half g_Xfc[64 * 1024];
__device__ __half g_Hst[3][2][64 * 1024];
__device__ float  g_Cst[3 * 64 * 1024];
__device__ unsigned g_count;
__device__ unsigned g_gen;

// ---------------- helpers ----------------
__device__ __forceinline__ float sigf(float v) { return 1.0f / (1.0f + expf(-v)); }

__device__ __forceinline__ unsigned smaddr(const void* p) {
    return (unsigned)__cvta_generic_to_shared(p);
}
__device__ __forceinline__ void cp16(unsigned dst, const void* src) {
    asm volatile("cp.async.cg.shared.global [%0], [%1], 16;" :: "r"(dst), "l"(src));
}
__device__ __forceinline__ void cp_commit() { asm volatile("cp.async.commit_group;"); }

__device__ __forceinline__ void ldsm4(unsigned& r0, unsigned& r1, unsigned& r2, unsigned& r3,
                                      unsigned addr) {
    asm volatile("ldmatrix.sync.aligned.m8n8.x4.shared.b16 {%0,%1,%2,%3}, [%4];"
                 : "=r"(r0), "=r"(r1), "=r"(r2), "=r"(r3) : "r"(addr));
}

__device__ __forceinline__ void mma16816(float c[4],
    unsigned a0, unsigned a1, unsigned a2, unsigned a3, unsigned b0, unsigned b1) {
    asm volatile(
        "mma.sync.aligned.m16n8k16.row.col.f32.f16.f16.f32 "
        "{%0,%1,%2,%3}, {%4,%5,%6,%7}, {%8,%9}, {%0,%1,%2,%3};"
        : "+f"(c[0]), "+f"(c[1]), "+f"(c[2]), "+f"(c[3])
        : "r"(a0), "r"(a1), "r"(a2), "r"(a3), "r"(b0), "r"(b1));
}

__device__ __forceinline__ void grid_sync() {
    __syncthreads();
    if (threadIdx.x == 0) {
        unsigned gen;
        asm volatile("ld.volatile.global.u32 %0, [%1];" : "=r"(gen) : "l"(&g_gen));
        unsigned arr;
        asm volatile("atom.release.gpu.global.add.u32 %0, [%1], %2;"
                     : "=r"(arr) : "l"(&g_count), "r"(1u));
        if (arr == NBLK - 1) {
            *(volatile unsigned*)&g_count = 0;
            asm volatile("red.release.gpu.global.add.u32 [%0], %1;"
                         :: "l"(&g_gen), "r"(1u));
        } else {
            unsigned cur;
            do {
                asm volatile("ld.acquire.gpu.global.u32 %0, [%1];"
                             : "=r"(cur) : "l"(&g_gen));
            } while (cur == gen);
        }
    }
    __syncthreads();
}

// ---------------- packing / init ----------------
// H-part FIRST: stage s < 16 covers k = Kin + s*64 (Whh); stages >= 16 cover Wih.
__global__ void pack_weights(const float* __restrict__ Wih, const float* __restrict__ Whh,
                             int layer, int Kin, int S) {
    __half* Wp = (layer == 0) ? g_Wp0 : (layer == 1) ? g_Wp1 : g_Wp2;
    int idx = blockIdx.x * blockDim.x + threadIdx.x;
    int total = 128 * S * 2048;
    if (idx >= total) return;
    int kk   = idx & 63;
    int col  = (idx >> 6) & 31;
    int rest = idx >> 11;
    int s    = rest % S;
    int bc   = rest / S;
    int row  = ((col >> 3) << 10) + bc * 8 + (col & 7);
    float v;
    if (s < 16) v = Whh[row * 1024 + s * 64 + kk];
    else        v = Wih[row * Kin + (s - 16) * 64 + kk];
    Wp[idx] = __float2half(v);
}

__global__ void pack_fc(const float* __restrict__ Wfc) {
    int i = blockIdx.x * blockDim.x + threadIdx.x;
    if (i < 128 * 1024) g_Wfch[i] = __float2half(Wfc[i]);
}

__global__ void init_state(const float* __restrict__ x, const float* __restrict__ h0,
                           const float* __restrict__ c0,
                           const float* __restrict__ bih0, const float* __restrict__ bhh0,
                           const float* __restrict__ bih1, const float* __restrict__ bhh1,
                           const float* __restrict__ bih2, const float* __restrict__ bhh2,
                           float* __restrict__ out) {
    int i = blockIdx.x * blockDim.x + threadIdx.x;
    if (i < 8192) { float v = x[i]; g_In0[i] = __float2half(v); out[i] = v; }
    if (i < 3 * 65536) {
        g_Hst[i >> 16][0][i & 65535] = __float2half(h0[i]);
        g_Cst[i] = c0[i];
    }
    if (i < 4096) {
        g_bsum[i]        = bih0[i] + bhh0[i];
        g_bsum[4096 + i] = bih1[i] + bhh1[i];
        g_bsum[8192 + i] = bih2[i] + bhh2[i];
    }
}

// ---------------- main persistent kernel ----------------
extern __shared__ __half sm_raw[];

struct CopyIdx {
    int ar0, au0, ar1, bcol, bu;
};

__device__ __forceinline__ void load_stage(
    const CopyIdx& ci, unsigned AsBase, unsigned BsBase,
    const __half* __restrict__ Hp, const __half* __restrict__ Xin, int ldX, int stagesH,
    const __half* __restrict__ Wblk, int s, int slot)
{
    unsigned adst = AsBase + (unsigned)(slot * ASTAGE) * 2u;
    unsigned bdst = BsBase + (unsigned)(slot * BSTAGE) * 2u;
    const __half* src; int ld;
    if (s < stagesH) { src = Hp + s * BK; ld = 1024; }
    else             { src = Xin + (s - stagesH) * BK; ld = ldX; }
    cp16(adst + (unsigned)(ci.ar0 * SA + ci.au0 * 8) * 2u, src + ci.ar0 * ld + ci.au0 * 8);
    cp16(adst + (unsigned)(ci.ar1 * SA + ci.au0 * 8) * 2u, src + ci.ar1 * ld + ci.au0 * 8);
    cp16(bdst + (unsigned)(ci.bcol * SA + ci.bu * 8) * 2u,
         Wblk + (size_t)s * 2048 + ci.bcol * 64 + ci.bu * 8);
}

// prologue: fill LA stages (all from H-part + weights; barrier-independent)
__device__ __forceinline__ void gemm_prologue(
    const CopyIdx& ci, unsigned AsBase, unsigned BsBase,
    const __half* __restrict__ Hp, const __half* __restrict__ Wblk)
{
#pragma unroll
    for (int s = 0; s < LA; ++s) {
        load_stage(ci, AsBase, BsBase, Hp, nullptr, 0, 32, Wblk, s, s);
        cp_commit();
    }
}

__device__ __forceinline__ void gemm_main(
    const CopyIdx& ci, unsigned AsBase, unsigned BsBase,
    const __half* __restrict__ Hp, const __half* __restrict__ Xin, int ldX, int stagesH,
    const __half* __restrict__ Wblk, int stages,
    const float* __restrict__ bsumL, float* __restrict__ Cl,
    __half* __restrict__ Hnext, __half* __restrict__ Xnext,
    int tid, int bc)
{
    float* gates = (float*)(sm_raw + GATES_OFF);
    const int lane = tid & 31, wid = tid >> 5;
    const int rt = wid & 3;
    const int cb = (wid >> 2) * 16;

    const int aRow = rt * 16 + ((lane >> 3) & 1) * 8 + (lane & 7);
    const unsigned aOff = (unsigned)(aRow * SA + (lane >> 4) * 8) * 2u;
    const int bRow = cb + ((lane >> 4) & 1) * 8 + (lane & 7);
    const unsigned bOff = (unsigned)(bRow * SA + ((lane >> 3) & 1) * 8) * 2u;

    float acc0[4] = {0.f, 0.f, 0.f, 0.f};
    float acc1[4] = {0.f, 0.f, 0.f, 0.f};

#pragma unroll 1
    for (int s = 0; s < stages; ++s) {
        asm volatile("cp.async.wait_group %0;" :: "n"(LA - 1));
        __syncthreads();
        if (s + LA < stages)
            load_stage(ci, AsBase, BsBase, Hp, Xin, ldX, stagesH, Wblk, s + LA, (s + LA) & (RING - 1));
        cp_commit();

        int slot = s & (RING - 1);
        unsigned aBase = AsBase + (unsigned)(slot * ASTAGE) * 2u + aOff;
        unsigned bBase = BsBase + (unsigned)(slot * BSTAGE) * 2u + bOff;
#pragma unroll
        for (int kk = 0; kk < 4; ++kk) {
            unsigned a0, a1, a2, a3, b00, b01, b10, b11;
            ldsm4(a0, a1, a2, a3, aBase + kk * 32u);
            ldsm4(b00, b01, b10, b11, bBase + kk * 32u);
            mma16816(acc0, a0, a1, a2, a3, b00, b01);
            mma16816(acc1, a0, a1, a2, a3, b10, b11);
        }
    }

    {
        int r = lane >> 2, p2 = (lane & 3) * 2;
        int row = rt * 16 + r, col = cb + p2;
        gates[row * 33 + col]           = acc0[0];
        gates[row * 33 + col + 1]       = acc0[1];
        gates[(row + 8) * 33 + col]     = acc0[2];
        gates[(row + 8) * 33 + col + 1] = acc0[3];
        gates[row * 33 + col + 8]       = acc1[0];
        gates[row * 33 + col + 9]       = acc1[1];
        gates[(row + 8) * 33 + col + 8] = acc1[2];
        gates[(row + 8) * 33 + col + 9] = acc1[3];
    }
    __syncthreads();

#pragma unroll
    for (int q = tid; q < 512; q += 256) {
        int b = q >> 3, nl = q & 7;
        int ng = bc * 8 + nl;
        float gi = gates[b * 33 + nl]       + bsumL[ng];
        float gf = gates[b * 33 + 8 + nl]   + bsumL[1024 + ng];
        float gg = gates[b * 33 + 16 + nl]  + bsumL[2048 + ng];
        float go = gates[b * 33 + 24 + nl]  + bsumL[3072 + ng];
        float c  = Cl[b * 1024 + ng];
        float cn = sigf(gf) * c + sigf(gi) * tanhf(gg);
        float h  = sigf(go) * tanhf(cn);
        Cl[b * 1024 + ng] = cn;
        __half hh = __float2half(h);
        Hnext[b * 1024 + ng] = hh;
        Xnext[b * 1024 + ng] = hh;
    }
    __syncthreads();   // all warps done with gates + ring before next prologue overwrites
}

__global__ void __launch_bounds__(NTHR, 1)
lstm_main(const float* __restrict__ x, const float* __restrict__ bfc,
          float* __restrict__ out)
{
    const int tid = threadIdx.x, bc = blockIdx.x;
    const unsigned AsBase = smaddr(sm_raw);
    const unsigned BsBase = smaddr(sm_raw + RING * ASTAGE);
    __half* sWfc = sm_raw + WFC_OFF;

    CopyIdx ci;
    ci.ar0 = tid >> 3; ci.au0 = tid & 7;
    ci.ar1 = (tid + 256) >> 3;
    ci.bcol = tid >> 3; ci.bu = tid & 7;

    // cache this CTA's fc weight slice in smem (8 rows x 1024)
    {
        const int cg = bc & 15;
        const __half* src = g_Wfch + cg * 8 * 1024;
#pragma unroll
        for (int i = 0; i < 4; ++i) {
            int e = (tid + i * 256) * 8;   // halves
            cp16(smaddr(sWfc + e), src + e);
        }
        cp_commit();
        asm volatile("cp.async.wait_group 0;");
        __syncthreads();
    }

    const __half* Wb0 = g_Wp0 + (size_t)bc * 18 * 2048;
    const __half* Wb1 = g_Wp1 + (size_t)bc * 32 * 2048;
    const __half* Wb2 = g_Wp2 + (size_t)bc * 32 * 2048;

#pragma unroll 1
    for (int t = 0; t < T_STEPS - 1; ++t) {
        int p = t & 1;

        // layer0 (prologue issued at end of previous iteration / below for t=0)
        if (t == 0) { gemm_prologue(ci, AsBase, BsBase, g_Hst[0][p], Wb0); grid_sync(); }
        gemm_main(ci, AsBase, BsBase, g_Hst[0][p], g_In0, 128, 16, Wb0, 18,
                  g_bsum, g_Cst, g_Hst[0][p ^ 1], g_X1, tid, bc);

        gemm_prologue(ci, AsBase, BsBase, g_Hst[1][p], Wb1);
        grid_sync();
        gemm_main(ci, AsBase, BsBase, g_Hst[1][p], g_X1, 1024, 16, Wb1, 32,
                  g_bsum + 4096, g_Cst + 65536, g_Hst[1][p ^ 1], g_X2, tid, bc);

        gemm_prologue(ci, AsBase, BsBase, g_Hst[2][p], Wb2);
        grid_sync();
        gemm_main(ci, AsBase, BsBase, g_Hst[2][p], g_X2, 1024, 16, Wb2, 32,
                  g_bsum + 8192, g_Cst + 131072, g_Hst[2][p ^ 1], g_Xfc, tid, bc);

        grid_sync();

        // fc phase: blocks tile 8(batch) x 16(cols); W from smem
        {
            int br = bc >> 4, cg = bc & 15;
            int o = tid >> 2, part = tid & 3;
            int b = br * 8 + (o >> 3);
            int dl = o & 7;
            int d = cg * 8 + dl;
            const float4* hp = (const float4*)(g_Xfc + b * 1024) + part * 32;
            const float4* wp = (const float4*)(sWfc + dl * 1024) + part * 32;
            float acc = 0.f;
#pragma unroll
            for (int k = 0; k < 32; ++k) {
                float4 hv = __ldcg(hp + k);
                float4 wv = wp[k];
                const __half2* h2 = (const __half2*)&hv;
                const __half2* w2 = (const __half2*)&wv;
#pragma unroll
                for (int j = 0; j < 4; ++j) {
                    float2 hf = __half22float2(h2[j]);
                    float2 wf = __half22float2(w2[j]);
                    acc = fmaf(hf.x, wf.x, acc);
                    acc = fmaf(hf.y, wf.y, acc);
                }
            }
            acc += __shfl_xor_sync(0xffffffff, acc, 1);
            acc += __shfl_xor_sync(0xffffffff, acc, 2);
            if (part == 0) {
                float z = sigf(acc + bfc[d]);
                float v = (t + 1 < PLEN) ? x[(size_t)(t + 1) * 8192 + b * 128 + d] : z;
                out[(size_t)(t + 1) * 8192 + b * 128 + d] = v;
                g_In0[b * 128 + d] = __float2half(v);
            }
        }
        __syncthreads();

        // prologue for NEXT step's layer0 (H-part of next phase + weights), then barrier
        if (t + 1 < T_STEPS - 1) {
            gemm_prologue(ci, AsBase, BsBase, g_Hst[0][(t + 1) & 1], Wb0);
        }
        grid_sync();
    }
}

// ---------------- launch ----------------
extern "C" void kernel_launch(void* const* d_in, const int* in_sizes, int n_in,
                              void* d_out, int out_size) {
    const float* x    = (const float*)d_in[0];
    const float* h0   = (const float*)d_in[1];
    const float* c0   = (const float*)d_in[2];
    const float* Wih0 = (const float*)d_in[3];
    const float* Whh0 = (const float*)d_in[4];
    const float* bih0 = (const float*)d_in[5];
    const float* bhh0 = (const float*)d_in[6];
    const float* Wih1 = (const float*)d_in[7];
    const float* Whh1 = (const float*)d_in[8];
    const float* bih1 = (const float*)d_in[9];
    const float* bhh1 = (const float*)d_in[10];
    const float* Wih2 = (const float*)d_in[11];
    const float* Whh2 = (const float*)d_in[12];
    const float* bih2 = (const float*)d_in[13];
    const float* bhh2 = (const float*)d_in[14];
    const float* Wfc  = (const float*)d_in[15];
    const float* bfc  = (const float*)d_in[16];
    float* out = (float*)d_out;

    static bool attr_done = false;
    if (!attr_done) {
        cudaFuncSetAttribute(lstm_main, cudaFuncAttributeMaxDynamicSharedMemorySize,
                             SMEM_BYTES);
        attr_done = true;
    }

    pack_weights<<<(128 * 18 * 2048 + 255) / 256, 256>>>(Wih0, Whh0, 0, 128, 18);
    pack_weights<<<(128 * 32 * 2048 + 255) / 256, 256>>>(Wih1, Whh1, 1, 1024, 32);
    pack_weights<<<(128 * 32 * 2048 + 255) / 256, 256>>>(Wih2, Whh2, 2, 1024, 32);
    pack_fc<<<512, 256>>>(Wfc);
    init_state<<<768, 256>>>(x, h0, c0, bih0, bhh0, bih1, bhh1, bih2, bhh2, out);
    lstm_main<<<NBLK, NTHR, SMEM_BYTES>>>(x, bfc, out);
}

// round 5
// speedup vs baseline: 1.0279x; 1.0279x over previous
#include <cuda_runtime.h>
#include <cuda_fp16.h>

#define NBLK 128
#define NTHR 512
#define T_STEPS 512
#define PLEN 64

#define BK 128                // k-halves per stage
#define RING 4
#define LA 3
#define SA 136                // smem row stride in halves (BK + 8)
#define ASTAGE (64 * SA)      // halves
#define BSTAGE (32 * SA)      // halves
#define GATES_OFF (RING * (ASTAGE + BSTAGE))          // halves
#define WFC_OFF   (GATES_OFF + 4 * 64 * 33 * 2)       // gates: 4 bufs of 64x33 floats
#define SMEM_BYTES ((WFC_OFF + 8 * 1024) * 2)

#define S0 9                  // layer0 stages: 8 H + 1 X (K=1152)
#define S12 16                // layers 1/2: 8 H + 8 X (K=2048)
#define L0SZ (128 * S0 * 4096)
#define L12SZ (128 * S12 * 4096)

// ---------------- device state ----------------
__device__ __half g_Wp0[L0SZ];
__device__ __half g_Wp1[L12SZ];
__device__ __half g_Wp2[L12SZ];
__device__ __half g_Wfch[128 * 1024];
__device__ float  g_bsum[3 * 4096];
__device__ __half g_In0[64 * 128];
__device__ __half g_X1[64 * 1024];
__device__ __half g_X2[64 * 1024];
__device__ __half g_Xfc[64 * 1024];
__device__ __half g_Hst[3][2][64 * 1024];
__device__ float  g_Cst[3 * 64 * 1024];
__device__ unsigned g_count;
__device__ unsigned g_gen;

// ---------------- helpers ----------------
__device__ __forceinline__ float sigf(float v) { return 1.0f / (1.0f + expf(-v)); }

__device__ __forceinline__ unsigned smaddr(const void* p) {
    return (unsigned)__cvta_generic_to_shared(p);
}
__device__ __forceinline__ void cp16(unsigned dst, const void* src) {
    asm volatile("cp.async.cg.shared.global [%0], [%1], 16;" :: "r"(dst), "l"(src));
}
__device__ __forceinline__ void cp_commit() { asm volatile("cp.async.commit_group;"); }

__device__ __forceinline__ void ldsm4(unsigned& r0, unsigned& r1, unsigned& r2, unsigned& r3,
                                      unsigned addr) {
    asm volatile("ldmatrix.sync.aligned.m8n8.x4.shared.b16 {%0,%1,%2,%3}, [%4];"
                 : "=r"(r0), "=r"(r1), "=r"(r2), "=r"(r3) : "r"(addr));
}

__device__ __forceinline__ void mma16816(float c[4],
    unsigned a0, unsigned a1, unsigned a2, unsigned a3, unsigned b0, unsigned b1) {
    asm volatile(
        "mma.sync.aligned.m16n8k16.row.col.f32.f16.f16.f32 "
        "{%0,%1,%2,%3}, {%4,%5,%6,%7}, {%8,%9}, {%0,%1,%2,%3};"
        : "+f"(c[0]), "+f"(c[1]), "+f"(c[2]), "+f"(c[3])
        : "r"(a0), "r"(a1), "r"(a2), "r"(a3), "r"(b0), "r"(b1));
}

__device__ __forceinline__ void grid_sync() {
    __syncthreads();
    if (threadIdx.x == 0) {
        unsigned gen;
        asm volatile("ld.volatile.global.u32 %0, [%1];" : "=r"(gen) : "l"(&g_gen));
        unsigned arr;
        asm volatile("atom.release.gpu.global.add.u32 %0, [%1], %2;"
                     : "=r"(arr) : "l"(&g_count), "r"(1u));
        if (arr == NBLK - 1) {
            *(volatile unsigned*)&g_count = 0;
            asm volatile("red.release.gpu.global.add.u32 [%0], %1;"
                         :: "l"(&g_gen), "r"(1u));
        } else {
            unsigned cur;
            do {
                asm volatile("ld.acquire.gpu.global.u32 %0, [%1];"
                             : "=r"(cur) : "l"(&g_gen));
            } while (cur == gen);
        }
    }
    __syncthreads();
}

// ---------------- packing / init ----------------
// Layout: Wp[((bc*S + s)*32 + col)*128 + kk]; col = gate*8 + nl; H-part first
// (s<8 -> Whh k=s*128+kk; s>=8 -> Wih k=(s-8)*128+kk).
__global__ void pack_all(const float* __restrict__ Wih0, const float* __restrict__ Whh0,
                         const float* __restrict__ Wih1, const float* __restrict__ Whh1,
                         const float* __restrict__ Wih2, const float* __restrict__ Whh2) {
    int idx = blockIdx.x * blockDim.x + threadIdx.x;
    const float *Wih, *Whh;
    __half* Wp;
    int S, Kin, i = idx;
    if (i < L0SZ)               { Wp = g_Wp0; S = S0;  Kin = 128;  Wih = Wih0; Whh = Whh0; }
    else if (i < L0SZ + L12SZ)  { i -= L0SZ;  Wp = g_Wp1; S = S12; Kin = 1024; Wih = Wih1; Whh = Whh1; }
    else if (i < L0SZ + 2*L12SZ){ i -= L0SZ + L12SZ; Wp = g_Wp2; S = S12; Kin = 1024; Wih = Wih2; Whh = Whh2; }
    else return;
    int kk   = i & 127;
    int col  = (i >> 7) & 31;
    int rest = i >> 12;
    int s    = rest % S;
    int bc   = rest / S;
    int row  = ((col >> 3) << 10) + bc * 8 + (col & 7);
    float v  = (s < 8) ? Whh[row * 1024 + s * 128 + kk]
                       : Wih[row * Kin + (s - 8) * 128 + kk];
    Wp[i] = __float2half(v);
}

__global__ void pack_fc(const float* __restrict__ Wfc) {
    int i = blockIdx.x * blockDim.x + threadIdx.x;
    if (i < 128 * 1024) g_Wfch[i] = __float2half(Wfc[i]);
}

__global__ void init_state(const float* __restrict__ x, const float* __restrict__ h0,
                           const float* __restrict__ c0,
                           const float* __restrict__ bih0, const float* __restrict__ bhh0,
                           const float* __restrict__ bih1, const float* __restrict__ bhh1,
                           const float* __restrict__ bih2, const float* __restrict__ bhh2,
                           float* __restrict__ out) {
    int i = blockIdx.x * blockDim.x + threadIdx.x;
    if (i < 8192) { float v = x[i]; g_In0[i] = __float2half(v); out[i] = v; }
    if (i < 3 * 65536) {
        g_Hst[i >> 16][0][i & 65535] = __float2half(h0[i]);
        g_Cst[i] = c0[i];
    }
    if (i < 4096) {
        g_bsum[i]        = bih0[i] + bhh0[i];
        g_bsum[4096 + i] = bih1[i] + bhh1[i];
        g_bsum[8192 + i] = bih2[i] + bhh2[i];
    }
}

// ---------------- main persistent kernel ----------------
extern __shared__ __half sm_raw[];

struct CopyIdx { int ar0, au0, ar1, bcol, bu; };

__device__ __forceinline__ void load_stage(
    const CopyIdx& ci, unsigned AsBase, unsigned BsBase,
    const __half* __restrict__ Hp, const __half* __restrict__ Xin, int ldX,
    const __half* __restrict__ Wblk, int s, int slot)
{
    unsigned adst = AsBase + (unsigned)(slot * ASTAGE) * 2u;
    unsigned bdst = BsBase + (unsigned)(slot * BSTAGE) * 2u;
    const __half* src; int ld;
    if (s < 8) { src = Hp + s * BK; ld = 1024; }
    else       { src = Xin + (s - 8) * BK; ld = ldX; }
    cp16(adst + (unsigned)(ci.ar0 * SA + ci.au0 * 8) * 2u, src + ci.ar0 * ld + ci.au0 * 8);
    cp16(adst + (unsigned)(ci.ar1 * SA + ci.au0 * 8) * 2u, src + ci.ar1 * ld + ci.au0 * 8);
    cp16(bdst + (unsigned)(ci.bcol * SA + ci.bu * 8) * 2u,
         Wblk + (size_t)s * 4096 + ci.bcol * 128 + ci.bu * 8);
}

__device__ __forceinline__ void gemm_prologue(
    const CopyIdx& ci, unsigned AsBase, unsigned BsBase,
    const __half* __restrict__ Hp, const __half* __restrict__ Wblk)
{
#pragma unroll
    for (int s = 0; s < LA; ++s) {       // all H-part: barrier-independent
        load_stage(ci, AsBase, BsBase, Hp, nullptr, 0, Wblk, s, s);
        cp_commit();
    }
}

__device__ __forceinline__ void gemm_main(
    const CopyIdx& ci, unsigned AsBase, unsigned BsBase,
    const __half* __restrict__ Hp, const __half* __restrict__ Xin, int ldX,
    const __half* __restrict__ Wblk, int stages,
    const float* __restrict__ bsumL, float* __restrict__ Cl,
    __half* __restrict__ Hnext, __half* __restrict__ Xnext,
    int tid, int bc)
{
    float* gates = (float*)(sm_raw + GATES_OFF);    // 4 buffers of 64x33
    const int lane = tid & 31, wid = tid >> 5;
    const int rt = wid & 3;          // row tile (16 rows)
    const int ks = wid >> 2;         // k-split 0..3 (kk pairs)

    // ldmatrix lane offsets (bytes, within a stage)
    const int aRow = rt * 16 + ((lane >> 3) & 1) * 8 + (lane & 7);
    const unsigned aOff = (unsigned)(aRow * SA + (lane >> 4) * 8) * 2u;
    const int bRowL = ((lane >> 4) & 1) * 8 + (lane & 7);
    const unsigned bOff = (unsigned)(bRowL * SA + ((lane >> 3) & 1) * 8) * 2u;

    float acc[2][2][4];
#pragma unroll
    for (int i = 0; i < 2; ++i)
#pragma unroll
        for (int j = 0; j < 2; ++j)
#pragma unroll
            for (int k = 0; k < 4; ++k) acc[i][j][k] = 0.f;

#pragma unroll 1
    for (int s = 0; s < stages; ++s) {
        asm volatile("cp.async.wait_group %0;" :: "n"(LA - 1));
        __syncthreads();
        if (s + LA < stages)
            load_stage(ci, AsBase, BsBase, Hp, Xin, ldX, Wblk, s + LA, (s + LA) & (RING - 1));
        cp_commit();

        int slot = s & (RING - 1);
        unsigned aBase = AsBase + (unsigned)(slot * ASTAGE) * 2u + aOff;
        unsigned bBase = BsBase + (unsigned)(slot * BSTAGE) * 2u + bOff;
#pragma unroll
        for (int j = 0; j < 2; ++j) {
            int kk = ks * 2 + j;
            unsigned a0, a1, a2, a3;
            ldsm4(a0, a1, a2, a3, aBase + kk * 32u);
#pragma unroll
            for (int hb = 0; hb < 2; ++hb) {
                unsigned b00, b01, b10, b11;
                ldsm4(b00, b01, b10, b11, bBase + hb * (16u * SA * 2u) + kk * 32u);
                mma16816(acc[hb][0], a0, a1, a2, a3, b00, b01);
                mma16816(acc[hb][1], a0, a1, a2, a3, b10, b11);
            }
        }
    }

    // store partial gates (per k-split buffer)
    {
        float* gk = gates + ks * (64 * 33);
        int r = lane >> 2, p2 = (lane & 3) * 2;
        int row = rt * 16 + r;
#pragma unroll
        for (int hb = 0; hb < 2; ++hb)
#pragma unroll
            for (int n8 = 0; n8 < 2; ++n8) {
                int col = hb * 16 + n8 * 8 + p2;
                float* q = acc[hb][n8];
                gk[row * 33 + col]           = q[0];
                gk[row * 33 + col + 1]       = q[1];
                gk[(row + 8) * 33 + col]     = q[2];
                gk[(row + 8) * 33 + col + 1] = q[3];
            }
    }
    __syncthreads();

    // fused LSTM cell epilogue: 512 threads, one (batch, hid) each
    {
        int b = tid >> 3, nl = tid & 7;
        int ng = bc * 8 + nl;
        int e = b * 33 + nl;
        float gi = 0.f, gf = 0.f, gg = 0.f, go = 0.f;
#pragma unroll
        for (int k = 0; k < 4; ++k) {
            const float* gk = gates + k * (64 * 33);
            gi += gk[e];
            gf += gk[e + 8];
            gg += gk[e + 16];
            go += gk[e + 24];
        }
        gi += bsumL[ng]; gf += bsumL[1024 + ng];
        gg += bsumL[2048 + ng]; go += bsumL[3072 + ng];
        float c  = Cl[b * 1024 + ng];
        float cn = sigf(gf) * c + sigf(gi) * tanhf(gg);
        float h  = sigf(go) * tanhf(cn);
        Cl[b * 1024 + ng] = cn;
        __half hh = __float2half(h);
        Hnext[b * 1024 + ng] = hh;
        Xnext[b * 1024 + ng] = hh;
    }
    __syncthreads();
}

__global__ void __launch_bounds__(NTHR, 1)
lstm_main(const float* __restrict__ x, const float* __restrict__ bfc,
          float* __restrict__ out)
{
    const int tid = threadIdx.x, bc = blockIdx.x;
    const unsigned AsBase = smaddr(sm_raw);
    const unsigned BsBase = smaddr(sm_raw + RING * ASTAGE);
    __half* sWfc = sm_raw + WFC_OFF;

    CopyIdx ci;
    ci.ar0 = tid >> 4;         ci.au0 = tid & 15;
    ci.ar1 = (tid + 512) >> 4;
    ci.bcol = tid >> 4;        ci.bu = tid & 15;

    // cache this CTA's fc weight slice in smem (8 rows x 1024 halves)
    {
        const int cg = bc & 15;
        const __half* src = g_Wfch + cg * 8 * 1024;
#pragma unroll
        for (int i = 0; i < 2; ++i) {
            int e = (tid + i * 512) * 8;
            cp16(smaddr(sWfc + e), src + e);
        }
        cp_commit();
        asm volatile("cp.async.wait_group 0;");
        __syncthreads();
    }

    const __half* Wb0 = g_Wp0 + (size_t)bc * S0 * 4096;
    const __half* Wb1 = g_Wp1 + (size_t)bc * S12 * 4096;
    const __half* Wb2 = g_Wp2 + (size_t)bc * S12 * 4096;

#pragma unroll 1
    for (int t = 0; t < T_STEPS - 1; ++t) {
        int p = t & 1;

        if (t == 0) { gemm_prologue(ci, AsBase, BsBase, g_Hst[0][p], Wb0); grid_sync(); }
        gemm_main(ci, AsBase, BsBase, g_Hst[0][p], g_In0, 128, Wb0, S0,
                  g_bsum, g_Cst, g_Hst[0][p ^ 1], g_X1, tid, bc);

        gemm_prologue(ci, AsBase, BsBase, g_Hst[1][p], Wb1);
        grid_sync();
        gemm_main(ci, AsBase, BsBase, g_Hst[1][p], g_X1, 1024, Wb1, S12,
                  g_bsum + 4096, g_Cst + 65536, g_Hst[1][p ^ 1], g_X2, tid, bc);

        gemm_prologue(ci, AsBase, BsBase, g_Hst[2][p], Wb2);
        grid_sync();
        gemm_main(ci, AsBase, BsBase, g_Hst[2][p], g_X2, 1024, Wb2, S12,
                  g_bsum + 8192, g_Cst + 131072, g_Hst[2][p ^ 1], g_Xfc, tid, bc);

        grid_sync();

        // fc: out = sigmoid(h2 @ Wfc^T + bfc); blocks tile 8(batch) x 16(cols)
        {
            int br = bc >> 4, cg = bc & 15;
            int o = tid >> 3, part = tid & 7;
            int b = br * 8 + (o >> 3);
            int dl = o & 7;
            int d = cg * 8 + dl;
            const float4* hp = (const float4*)(g_Xfc + b * 1024) + part * 16;
            const float4* wp = (const float4*)(sWfc + dl * 1024) + part * 16;
            float acc = 0.f;
#pragma unroll
            for (int k = 0; k < 16; ++k) {
                float4 hv = __ldcg(hp + k);
                float4 wv = wp[k];
                const __half2* h2 = (const __half2*)&hv;
                const __half2* w2 = (const __half2*)&wv;
#pragma unroll
                for (int j = 0; j < 4; ++j) {
                    float2 hf = __half22float2(h2[j]);
                    float2 wf = __half22float2(w2[j]);
                    acc = fmaf(hf.x, wf.x, acc);
                    acc = fmaf(hf.y, wf.y, acc);
                }
            }
            acc += __shfl_xor_sync(0xffffffff, acc, 1);
            acc += __shfl_xor_sync(0xffffffff, acc, 2);
            acc += __shfl_xor_sync(0xffffffff, acc, 4);
            if (part == 0) {
                float z = sigf(acc + bfc[d]);
                float v = (t + 1 < PLEN) ? x[(size_t)(t + 1) * 8192 + b * 128 + d] : z;
                out[(size_t)(t + 1) * 8192 + b * 128 + d] = v;
                g_In0[b * 128 + d] = __float2half(v);
            }
        }
        __syncthreads();

        if (t + 1 < T_STEPS - 1)
            gemm_prologue(ci, AsBase, BsBase, g_Hst[0][(t + 1) & 1], Wb0);
        grid_sync();
    }
}

// ---------------- launch (lstm_main is launch #4 so ncu captures it) ----------------
extern "C" void kernel_launch(void* const* d_in, const int* in_sizes, int n_in,
                              void* d_out, int out_size) {
    const float* x    = (const float*)d_in[0];
    const float* h0   = (const float*)d_in[1];
    const float* c0   = (const float*)d_in[2];
    const float* Wih0 = (const float*)d_in[3];
    const float* Whh0 = (const float*)d_in[4];
    const float* bih0 = (const float*)d_in[5];
    const float* bhh0 = (const float*)d_in[6];
    const float* Wih1 = (const float*)d_in[7];
    const float* Whh1 = (const float*)d_in[8];
    const float* bih1 = (const float*)d_in[9];
    const float* bhh1 = (const float*)d_in[10];
    const float* Wih2 = (const float*)d_in[11];
    const float* Whh2 = (const float*)d_in[12];
    const float* bih2 = (const float*)d_in[13];
    const float* bhh2 = (const float*)d_in[14];
    const float* Wfc  = (const float*)d_in[15];
    const float* bfc  = (const float*)d_in[16];
    float* out = (float*)d_out;

    static bool attr_done = false;
    if (!attr_done) {
        cudaFuncSetAttribute(lstm_main, cudaFuncAttributeMaxDynamicSharedMemorySize,
                             SMEM_BYTES);
        attr_done = true;
    }

    int total = L0SZ + 2 * L12SZ;
    pack_all<<<(total + 255) / 256, 256>>>(Wih0, Whh0, Wih1, Whh1, Wih2, Whh2);
    pack_fc<<<512, 256>>>(Wfc);
    init_state<<<768, 256>>>(x, h0, c0, bih0, bhh0, bih1, bhh1, bih2, bhh2, out);
    lstm_main<<<NBLK, NTHR, SMEM_BYTES>>>(x, bfc, out);
}